// round 3
// baseline (speedup 1.0000x reference)
#include <cuda_runtime.h>

// SyntheticTripletLoss closed form: per valid row only
//   pp=<p,p>, tt=<t,t>, pt=<p,t>
//   sim_pn = (pp - pt^2) / max(sqrt(pp - 2pt^2 + pt^2*tt), EPS)
//   loss   = max(MARGIN + sim_pn - pt, 0); mean over valid rows.
// One fused kernel. Each warp handles 2 rows: (w, w+8192) = (b, b+16) at the
// same t — anti-correlated validity (lengths sorted desc) balances work, and
// 16 LDG.128 per warp are in flight before any consumption (2x MLP vs R2).

#define MARGIN 0.5f
#define EPS_N 1e-12f

static constexpr int B = 32;
static constexpr int T = 512;
static constexpr int D = 512;
static constexpr int WARPS_PER_BLOCK = 8;
static constexpr int THREADS = WARPS_PER_BLOCK * 32;        // 256
static constexpr int ROWS = B * T;                          // 16384
static constexpr int HALF = ROWS / 2;                       // 8192
static constexpr int NBLOCKS = HALF / WARPS_PER_BLOCK;      // 1024

__device__ float g_partials[NBLOCKS];
__device__ unsigned int g_ticket;   // zero-init; last block resets each run

__device__ __forceinline__ float row_loss(float pp, float tt, float pt) {
    float pt2  = pt * pt;
    float n2   = fmaxf(pp - 2.0f * pt2 + pt2 * tt, 0.0f);
    float norm = fmaxf(sqrtf(n2), EPS_N);
    return fmaxf(MARGIN + (pp - pt2) / norm - pt, 0.0f);
}

__global__ __launch_bounds__(THREADS)
void triplet_fused_kernel(const float* __restrict__ preds,
                          const float* __restrict__ targets,
                          const int* __restrict__ lengths,
                          float* __restrict__ out) {
    const int warp = threadIdx.x >> 5;
    const int lane = threadIdx.x & 31;
    const int w    = blockIdx.x * WARPS_PER_BLOCK + warp;   // [0, 8192)
    const int t    = w & (T - 1);
    const int b0   = w >> 9;          // [0, 16)
    const int b1   = b0 + 16;         // [16, 32)
    const int row0 = w;               // b0 * T + t
    const int row1 = w + HALF;        // b1 * T + t

    const bool v0 = t < __ldg(&lengths[b0]);
    const bool v1 = t < __ldg(&lengths[b1]);

    // ---- issue ALL loads before any consumption (warp-uniform branches) ----
    float4 a0, a1, a2, a3, c0, c1, c2, c3;   // row0: preds / targets
    float4 d0, d1, d2, d3, e0, e1, e2, e3;   // row1: preds / targets

    if (v0) {
        const float4* __restrict__ p4 =
            reinterpret_cast<const float4*>(preds + (size_t)row0 * D);
        const float4* __restrict__ t4 =
            reinterpret_cast<const float4*>(targets + (size_t)row0 * D);
        a0 = __ldg(p4 + lane);      a1 = __ldg(p4 + lane + 32);
        a2 = __ldg(p4 + lane + 64); a3 = __ldg(p4 + lane + 96);
        c0 = __ldg(t4 + lane);      c1 = __ldg(t4 + lane + 32);
        c2 = __ldg(t4 + lane + 64); c3 = __ldg(t4 + lane + 96);
    }
    if (v1) {
        const float4* __restrict__ p4 =
            reinterpret_cast<const float4*>(preds + (size_t)row1 * D);
        const float4* __restrict__ t4 =
            reinterpret_cast<const float4*>(targets + (size_t)row1 * D);
        d0 = __ldg(p4 + lane);      d1 = __ldg(p4 + lane + 32);
        d2 = __ldg(p4 + lane + 64); d3 = __ldg(p4 + lane + 96);
        e0 = __ldg(t4 + lane);      e1 = __ldg(t4 + lane + 32);
        e2 = __ldg(t4 + lane + 64); e3 = __ldg(t4 + lane + 96);
    }

    #define ACC(pp, tt, pt, a, c)                                              \
        pp = fmaf(a.x, a.x, fmaf(a.y, a.y, fmaf(a.z, a.z, fmaf(a.w, a.w, pp)))); \
        tt = fmaf(c.x, c.x, fmaf(c.y, c.y, fmaf(c.z, c.z, fmaf(c.w, c.w, tt)))); \
        pt = fmaf(a.x, c.x, fmaf(a.y, c.y, fmaf(a.z, c.z, fmaf(a.w, c.w, pt))));

    float loss = 0.0f;
    float pp0 = 0.f, tt0 = 0.f, pt0 = 0.f;
    float pp1 = 0.f, tt1 = 0.f, pt1 = 0.f;
    if (v0) { ACC(pp0, tt0, pt0, a0, c0) ACC(pp0, tt0, pt0, a1, c1)
              ACC(pp0, tt0, pt0, a2, c2) ACC(pp0, tt0, pt0, a3, c3) }
    if (v1) { ACC(pp1, tt1, pt1, d0, e0) ACC(pp1, tt1, pt1, d1, e1)
              ACC(pp1, tt1, pt1, d2, e2) ACC(pp1, tt1, pt1, d3, e3) }
    #undef ACC

    if (v0 | v1) {
        #pragma unroll
        for (int off = 16; off; off >>= 1) {
            pp0 += __shfl_xor_sync(0xffffffffu, pp0, off);
            tt0 += __shfl_xor_sync(0xffffffffu, tt0, off);
            pt0 += __shfl_xor_sync(0xffffffffu, pt0, off);
            pp1 += __shfl_xor_sync(0xffffffffu, pp1, off);
            tt1 += __shfl_xor_sync(0xffffffffu, tt1, off);
            pt1 += __shfl_xor_sync(0xffffffffu, pt1, off);
        }
        if (v0) loss += row_loss(pp0, tt0, pt0);
        if (v1) loss += row_loss(pp1, tt1, pt1);
    }

    // ---- block partial (deterministic fixed slot) + fence-and-ticket ----
    __shared__ float s_warp[WARPS_PER_BLOCK];
    __shared__ bool  s_is_last;
    if (lane == 0) s_warp[warp] = loss;
    __syncthreads();

    if (threadIdx.x == 0) {
        float sum = 0.f;
        #pragma unroll
        for (int i = 0; i < WARPS_PER_BLOCK; i++) sum += s_warp[i];
        g_partials[blockIdx.x] = sum;
        __threadfence();
        unsigned int ticket = atomicAdd(&g_ticket, 1u);
        s_is_last = (ticket == (unsigned int)(NBLOCKS - 1));
    }
    __syncthreads();
    if (!s_is_last) return;

    // Last block: reduce 1024 partials in fixed order.
    __shared__ float s_red[THREADS];
    float sum = 0.f;
    #pragma unroll
    for (int k = 0; k < NBLOCKS / THREADS; k++)
        sum += __ldcg(&g_partials[threadIdx.x + k * THREADS]);
    s_red[threadIdx.x] = sum;
    __syncthreads();
    #pragma unroll
    for (int off = THREADS / 2; off; off >>= 1) {
        if (threadIdx.x < off) s_red[threadIdx.x] += s_red[threadIdx.x + off];
        __syncthreads();
    }
    if (threadIdx.x == 0) {
        int cnt = 0;
        #pragma unroll
        for (int i = 0; i < B; i++) cnt += __ldg(&lengths[i]);
        out[0] = s_red[0] / (float)cnt;
        g_ticket = 0;   // reset for next graph replay
    }
}

extern "C" void kernel_launch(void* const* d_in, const int* in_sizes, int n_in,
                              void* d_out, int out_size) {
    const float* preds   = (const float*)d_in[0];
    const float* targets = (const float*)d_in[1];
    const int*   lengths = (const int*)d_in[2];
    float* out = (float*)d_out;

    triplet_fused_kernel<<<NBLOCKS, THREADS>>>(preds, targets, lengths, out);
}

// round 4
// speedup vs baseline: 1.1545x; 1.1545x over previous
#include <cuda_runtime.h>

// SyntheticTripletLoss closed form: per valid row only
//   pp=<p,p>, tt=<t,t>, pt=<p,t>
//   sim_pn = (pp - pt^2) / max(sqrt(pp - 2pt^2 + pt^2*tt), EPS)
//   loss   = max(MARGIN + sim_pn - pt, 0); mean over valid rows.
//
// Single launch, single co-resident wave (296 CTAs), grid-stride per warp.
// Sync via release-atomic ticket (NO gpu-scope threadfence -> no CCTL.IVALL
// L1 flushes, which is what cost R2/R3 ~8us).

#define MARGIN 0.5f
#define EPS_N 1e-12f

static constexpr int B = 32;
static constexpr int T = 512;
static constexpr int D = 512;
static constexpr int ROWS = B * T;                 // 16384
static constexpr int NBLK = 296;                   // 2 CTAs/SM, one wave
static constexpr int THREADS = 256;                // 8 warps
static constexpr int TOTAL_WARPS = NBLK * (THREADS / 32);  // 2368

__device__ float g_partials[NBLK];
__device__ unsigned int g_ticket;   // zero-init; last block resets each run

__device__ __forceinline__ float row_loss(float pp, float tt, float pt) {
    float pt2  = pt * pt;
    float n2   = fmaxf(pp - 2.0f * pt2 + pt2 * tt, 0.0f);
    float norm = fmaxf(sqrtf(n2), EPS_N);
    return fmaxf(MARGIN + (pp - pt2) / norm - pt, 0.0f);
}

__global__ __launch_bounds__(THREADS)
void triplet_persistent_kernel(const float* __restrict__ preds,
                               const float* __restrict__ targets,
                               const int* __restrict__ lengths,
                               float* __restrict__ out) {
    __shared__ int   s_len[B];
    __shared__ float s_warp[THREADS / 32];
    __shared__ bool  s_is_last;

    if (threadIdx.x < B) s_len[threadIdx.x] = lengths[threadIdx.x];
    __syncthreads();

    const int warp = threadIdx.x >> 5;
    const int lane = threadIdx.x & 31;
    const int gw   = blockIdx.x * (THREADS / 32) + warp;

    float acc = 0.0f;

    for (int row = gw; row < ROWS; row += TOTAL_WARPS) {
        const int b = row >> 9;        // row / T
        const int t = row & (T - 1);   // row % T
        if (t >= s_len[b]) continue;   // skip: zero memory traffic

        const float4* __restrict__ p4 =
            reinterpret_cast<const float4*>(preds + (size_t)row * D);
        const float4* __restrict__ t4 =
            reinterpret_cast<const float4*>(targets + (size_t)row * D);

        // 4 float4 per lane per tensor; front-batch all 8 loads for MLP.
        float4 a0 = __ldg(p4 + lane);
        float4 a1 = __ldg(p4 + lane + 32);
        float4 a2 = __ldg(p4 + lane + 64);
        float4 a3 = __ldg(p4 + lane + 96);
        float4 c0 = __ldg(t4 + lane);
        float4 c1 = __ldg(t4 + lane + 32);
        float4 c2 = __ldg(t4 + lane + 64);
        float4 c3 = __ldg(t4 + lane + 96);

        float pp = 0.f, tt = 0.f, pt = 0.f;
        #define ACC(a, c)                                                        \
            pp = fmaf(a.x, a.x, fmaf(a.y, a.y, fmaf(a.z, a.z, fmaf(a.w, a.w, pp)))); \
            tt = fmaf(c.x, c.x, fmaf(c.y, c.y, fmaf(c.z, c.z, fmaf(c.w, c.w, tt)))); \
            pt = fmaf(a.x, c.x, fmaf(a.y, c.y, fmaf(a.z, c.z, fmaf(a.w, c.w, pt))));
        ACC(a0, c0) ACC(a1, c1) ACC(a2, c2) ACC(a3, c3)
        #undef ACC

        #pragma unroll
        for (int off = 16; off; off >>= 1) {
            pp += __shfl_xor_sync(0xffffffffu, pp, off);
            tt += __shfl_xor_sync(0xffffffffu, tt, off);
            pt += __shfl_xor_sync(0xffffffffu, pt, off);
        }
        acc += row_loss(pp, tt, pt);   // identical across lanes
    }

    // ---- block partial (fixed slot: deterministic) ----
    if (lane == 0) s_warp[warp] = acc;
    __syncthreads();

    if (threadIdx.x == 0) {
        float sum = 0.f;
        #pragma unroll
        for (int i = 0; i < THREADS / 32; i++) sum += s_warp[i];
        g_partials[blockIdx.x] = sum;
        // Release-scoped ticket: orders the partial store without a full
        // gpu-scope MEMBAR (no L1D flush). Acquire side pairs with the
        // last block's L2 reads below.
        unsigned int old;
        asm volatile("atom.acq_rel.gpu.global.add.u32 %0, [%1], 1;"
                     : "=r"(old) : "l"(&g_ticket) : "memory");
        s_is_last = (old == (unsigned int)(NBLK - 1));
    }
    __syncthreads();
    if (!s_is_last) return;

    // ---- last block: reduce 296 partials (L2-resident), fixed order ----
    __shared__ float s_red[THREADS];
    float sum = 0.f;
    for (int i = threadIdx.x; i < NBLK; i += THREADS)
        sum += __ldcg(&g_partials[i]);   // L2 path: bypass (flushed) L1
    s_red[threadIdx.x] = sum;
    __syncthreads();
    #pragma unroll
    for (int off = THREADS / 2; off; off >>= 1) {
        if (threadIdx.x < off) s_red[threadIdx.x] += s_red[threadIdx.x + off];
        __syncthreads();
    }
    if (threadIdx.x == 0) {
        int cnt = 0;
        #pragma unroll
        for (int i = 0; i < B; i++) cnt += s_len[i];
        out[0] = s_red[0] / (float)cnt;
        g_ticket = 0;   // reset for next graph replay
    }
}

extern "C" void kernel_launch(void* const* d_in, const int* in_sizes, int n_in,
                              void* d_out, int out_size) {
    const float* preds   = (const float*)d_in[0];
    const float* targets = (const float*)d_in[1];
    const int*   lengths = (const int*)d_in[2];
    float* out = (float*)d_out;

    triplet_persistent_kernel<<<NBLK, THREADS>>>(preds, targets, lengths, out);
}